// round 1
// baseline (speedup 1.0000x reference)
#include <cuda_runtime.h>
#include <cstdint>

#define N_NODES 100000
#define N_EDGES 400000
#define HID 256
#define NT 54

// Scratch for Wx = x @ W_if^T  (100000 x 256 fp32 = 102.4 MB)
__device__ float g_Wx[(size_t)N_NODES * HID];

__device__ __forceinline__ float f2tf32(float x) {
    uint32_t u;
    asm("cvt.rna.tf32.f32 %0, %1;" : "=r"(u) : "f"(x));
    return __uint_as_float(u);
}

// ---------------------------------------------------------------------------
// Kernel A: Wx[n][h] = sum_v x[n][v] * W_if[h][v]
// Block: 256 threads, 32 nodes. W_if transposed into smem, x tile in smem.
// Thread computes 8 nodes x 4 cols (float4 W reads, broadcast x reads).
// ---------------------------------------------------------------------------
__global__ void __launch_bounds__(256) wx_kernel(const float* __restrict__ x,
                                                 const float* __restrict__ W_if)
{
    extern __shared__ float sm[];
    float* xs = sm;                  // [32][54]
    float* Wt = sm + 32 * NT;        // [54][260] (padded, transposed W_if)
    const int tid = threadIdx.x;
    const int n0 = blockIdx.x * 32;

    for (int i = tid; i < 32 * NT; i += 256) xs[i] = x[(size_t)n0 * NT + i];
    for (int i = tid; i < HID * NT; i += 256) {
        int c = i / NT, v = i % NT;
        Wt[v * 260 + c] = W_if[i];
    }
    __syncthreads();

    const int u  = tid & 63;
    const int c0 = u * 4;
    const int ng = tid >> 6;

    float acc[8][4];
    #pragma unroll
    for (int i = 0; i < 8; ++i)
        #pragma unroll
        for (int j = 0; j < 4; ++j) acc[i][j] = 0.f;

    #pragma unroll 2
    for (int v = 0; v < NT; ++v) {
        float4 w = *reinterpret_cast<const float4*>(&Wt[v * 260 + c0]);
        #pragma unroll
        for (int i = 0; i < 8; ++i) {
            float xv = xs[(ng * 8 + i) * NT + v];
            acc[i][0] += xv * w.x;
            acc[i][1] += xv * w.y;
            acc[i][2] += xv * w.z;
            acc[i][3] += xv * w.w;
        }
    }

    #pragma unroll
    for (int i = 0; i < 8; ++i) {
        int row = n0 + ng * 8 + i;
        float4 o = make_float4(acc[i][0], acc[i][1], acc[i][2], acc[i][3]);
        *reinterpret_cast<float4*>(&g_Wx[(size_t)row * HID + c0]) = o;
    }
}

// ---------------------------------------------------------------------------
// Kernel B: fused  Uh = h_all @ W_hf^T  (tf32 mma.sync, BM=64 BN=256 BK=32)
//           + epilogue: f = sigmoid(Wx[seg]+Uh+b_f); out[seg] += f * c_all
// 256 threads = 8 warps arranged 2(m) x 4(n); each warp: 32x64 tile.
// Epilogue: stage Uh tile [64][260] in smem; thread t owns column t and does a
// run-length segmented sum over the 64 sorted edges, atomicAdd per flush.
// ---------------------------------------------------------------------------
__global__ void __launch_bounds__(256) fused_kernel(
    const float* __restrict__ h_all, const float* __restrict__ c_all,
    const int*   __restrict__ seg,   const float* __restrict__ W_hf,
    const float* __restrict__ b_f,   float* __restrict__ out)
{
    extern __shared__ float sm[];
    float* As = sm;              // [64][36]  h tile (tf32)
    float* Bs = sm + 64 * 36;    // [256][36] W_hf tile (tf32), row n, col k
    __shared__ int s_seg[64];

    const int tid  = threadIdx.x;
    const int lane = tid & 31;
    const int warp = tid >> 5;
    const int wm = warp >> 2, wn = warp & 3;
    const int g  = lane >> 2, tg = lane & 3;
    const size_t e0 = (size_t)blockIdx.x * 64;

    if (tid < 64) s_seg[tid] = seg[e0 + tid];

    float acc[2][8][4];
    #pragma unroll
    for (int i = 0; i < 2; ++i)
        #pragma unroll
        for (int j = 0; j < 8; ++j)
            #pragma unroll
            for (int q = 0; q < 4; ++q) acc[i][j][q] = 0.f;

    for (int kt = 0; kt < 8; ++kt) {
        const int k0 = kt * 32;
        if (kt) __syncthreads();

        // A tile: 64 rows x 32 k of h_all
        #pragma unroll
        for (int r = 0; r < 2; ++r) {
            int idx = tid + 256 * r;
            int row = idx >> 3, cf = (idx & 7) * 4;
            float4 v = *reinterpret_cast<const float4*>(
                &h_all[(e0 + row) * HID + k0 + cf]);
            float* d = &As[row * 36 + cf];
            d[0] = f2tf32(v.x); d[1] = f2tf32(v.y);
            d[2] = f2tf32(v.z); d[3] = f2tf32(v.w);
        }
        // B tile: 256 rows(n=h) x 32 k of W_hf
        #pragma unroll
        for (int r = 0; r < 8; ++r) {
            int idx = tid + 256 * r;
            int n = idx >> 3, cf = (idx & 7) * 4;
            float4 v = *reinterpret_cast<const float4*>(
                &W_hf[(size_t)n * HID + k0 + cf]);
            float* d = &Bs[n * 36 + cf];
            d[0] = f2tf32(v.x); d[1] = f2tf32(v.y);
            d[2] = f2tf32(v.z); d[3] = f2tf32(v.w);
        }
        __syncthreads();

        #pragma unroll
        for (int k8 = 0; k8 < 4; ++k8) {
            const int kb = k8 * 8;
            uint32_t a[2][4], b[8][2];
            #pragma unroll
            for (int i = 0; i < 2; ++i) {
                int rm = wm * 32 + i * 16;
                a[i][0] = __float_as_uint(As[(rm + g    ) * 36 + kb + tg    ]);
                a[i][1] = __float_as_uint(As[(rm + g + 8) * 36 + kb + tg    ]);
                a[i][2] = __float_as_uint(As[(rm + g    ) * 36 + kb + tg + 4]);
                a[i][3] = __float_as_uint(As[(rm + g + 8) * 36 + kb + tg + 4]);
            }
            #pragma unroll
            for (int j = 0; j < 8; ++j) {
                int cn = wn * 64 + j * 8 + g;
                b[j][0] = __float_as_uint(Bs[cn * 36 + kb + tg    ]);
                b[j][1] = __float_as_uint(Bs[cn * 36 + kb + tg + 4]);
            }
            #pragma unroll
            for (int i = 0; i < 2; ++i)
                #pragma unroll
                for (int j = 0; j < 8; ++j) {
                    asm volatile(
                        "mma.sync.aligned.m16n8k8.row.col.f32.tf32.tf32.f32 "
                        "{%0,%1,%2,%3},{%4,%5,%6,%7},{%8,%9},{%0,%1,%2,%3};"
                        : "+f"(acc[i][j][0]), "+f"(acc[i][j][1]),
                          "+f"(acc[i][j][2]), "+f"(acc[i][j][3])
                        : "r"(a[i][0]), "r"(a[i][1]), "r"(a[i][2]), "r"(a[i][3]),
                          "r"(b[j][0]), "r"(b[j][1]));
                }
        }
    }
    __syncthreads();

    // Stage Uh tile to smem: Sm[64][260]
    float* Sm = sm;
    #pragma unroll
    for (int i = 0; i < 2; ++i)
        #pragma unroll
        for (int j = 0; j < 8; ++j) {
            int row = wm * 32 + i * 16 + g;
            int col = wn * 64 + j * 8 + tg * 2;
            Sm[row * 260 + col]           = acc[i][j][0];
            Sm[row * 260 + col + 1]       = acc[i][j][1];
            Sm[(row + 8) * 260 + col]     = acc[i][j][2];
            Sm[(row + 8) * 260 + col + 1] = acc[i][j][3];
        }
    __syncthreads();

    // Column-wise run-length segmented reduction over sorted seg
    const int t = tid;
    const float bf = b_f[t];
    int prev = -1;
    float accu = 0.f;
    for (int e = 0; e < 64; ++e) {
        int node = s_seg[e];
        if (node != prev) {
            if (prev >= 0) atomicAdd(&out[(size_t)prev * HID + t], accu);
            accu = 0.f;
            prev = node;
        }
        float z = Sm[e * 260 + t] + bf + g_Wx[(size_t)node * HID + t];
        float f = 1.0f / (1.0f + __expf(-z));
        accu += f * c_all[(e0 + e) * HID + t];
    }
    atomicAdd(&out[(size_t)prev * HID + t], accu);
}

// ---------------------------------------------------------------------------
extern "C" void kernel_launch(void* const* d_in, const int* in_sizes, int n_in,
                              void* d_out, int out_size)
{
    const float* x     = (const float*)d_in[0];
    const float* h_all = (const float*)d_in[1];
    const float* c_all = (const float*)d_in[2];
    const int*   seg   = (const int*)  d_in[3];
    const float* W_if  = (const float*)d_in[4];
    const float* W_hf  = (const float*)d_in[5];
    const float* b_f   = (const float*)d_in[6];
    float* out = (float*)d_out;

    const int smemA = (32 * NT + NT * 260) * (int)sizeof(float);   // 63072
    const int smemB = (64 * 260) * (int)sizeof(float);             // 66560

    cudaFuncSetAttribute(wx_kernel,
        cudaFuncAttributeMaxDynamicSharedMemorySize, smemA);
    cudaFuncSetAttribute(fused_kernel,
        cudaFuncAttributeMaxDynamicSharedMemorySize, smemB);

    cudaMemsetAsync(d_out, 0, (size_t)out_size * sizeof(float));
    wx_kernel<<<N_NODES / 32, 256, smemA>>>(x, W_if);
    fused_kernel<<<N_EDGES / 64, 256, smemB>>>(h_all, c_all, seg, W_hf, b_f, out);
}

// round 3
// speedup vs baseline: 1.1470x; 1.1470x over previous
#include <cuda_runtime.h>
#include <cstdint>

#define N_NODES 100000
#define N_EDGES 400000
#define HID 256
#define NT 54

// Scratch for Wx = x @ W_if^T  (100000 x 256 fp32 = 102.4 MB)
__device__ float g_Wx[(size_t)N_NODES * HID];

// ---------------------------------------------------------------------------
#define CP16(dst, src) \
    asm volatile("cp.async.cg.shared.global [%0], [%1], 16;" \
                 :: "r"(dst), "l"(src) : "memory")
#define CP_COMMIT()  asm volatile("cp.async.commit_group;" ::: "memory")
#define CP_WAIT2()   asm volatile("cp.async.wait_group 2;" ::: "memory")

__device__ __forceinline__ uint32_t smem_u32(const void* p) {
    uint32_t a;
    asm("{ .reg .u64 t; cvta.to.shared.u64 t, %1; cvt.u32.u64 %0, t; }"
        : "=r"(a) : "l"(p));
    return a;
}

// ---------------------------------------------------------------------------
// Kernel A: Wx[n][h] = sum_v x[n][v] * W_if[h][v]
// ---------------------------------------------------------------------------
__global__ void __launch_bounds__(256) wx_kernel(const float* __restrict__ x,
                                                 const float* __restrict__ W_if)
{
    extern __shared__ float sm[];
    float* xs = sm;                  // [32][54]
    float* Wt = sm + 32 * NT;        // [54][260]
    const int tid = threadIdx.x;
    const int n0 = blockIdx.x * 32;

    for (int i = tid; i < 32 * NT; i += 256) xs[i] = x[(size_t)n0 * NT + i];
    for (int i = tid; i < HID * NT; i += 256) {
        int c = i / NT, v = i % NT;
        Wt[v * 260 + c] = W_if[i];
    }
    __syncthreads();

    const int u  = tid & 63;
    const int c0 = u * 4;
    const int ng = tid >> 6;

    float acc[8][4];
    #pragma unroll
    for (int i = 0; i < 8; ++i)
        #pragma unroll
        for (int j = 0; j < 4; ++j) acc[i][j] = 0.f;

    #pragma unroll 2
    for (int v = 0; v < NT; ++v) {
        float4 w = *reinterpret_cast<const float4*>(&Wt[v * 260 + c0]);
        #pragma unroll
        for (int i = 0; i < 8; ++i) {
            float xv = xs[(ng * 8 + i) * NT + v];
            acc[i][0] += xv * w.x;
            acc[i][1] += xv * w.y;
            acc[i][2] += xv * w.z;
            acc[i][3] += xv * w.w;
        }
    }

    #pragma unroll
    for (int i = 0; i < 8; ++i) {
        int row = n0 + ng * 8 + i;
        float4 o = make_float4(acc[i][0], acc[i][1], acc[i][2], acc[i][3]);
        *reinterpret_cast<float4*>(&g_Wx[(size_t)row * HID + c0]) = o;
    }
}

// ---------------------------------------------------------------------------
// Kernel B: tf32 mma.sync GEMM (BM=128, BN=128, BK=32, 3-stage cp.async)
//           + fused sigmoid/segment-sum epilogue.
// Grid: (3125, 2). 256 threads = 8 warps, 4(m) x 2(n), warp tile 32x64.
// ---------------------------------------------------------------------------
#define BM 128
#define BN 128
#define BK 32
#define LDT 36                         // padded row pitch (floats)
#define STG_FLTS ((BM + BN) * LDT)     // 9216 floats = 36864 B
#define NSTAGE 3
#define SMEM_DYN (NSTAGE * STG_FLTS * 4)

__global__ void __launch_bounds__(256, 2) fused_mma(
    const float* __restrict__ h_all, const float* __restrict__ c_all,
    const int*   __restrict__ seg,   const float* __restrict__ W_hf,
    const float* __restrict__ b_f,   float* __restrict__ out)
{
    extern __shared__ float sm[];
    __shared__ int s_seg[BM];

    const int tid  = threadIdx.x;
    const int lane = tid & 31;
    const int warp = tid >> 5;
    const int wm = warp >> 1;          // 0..3
    const int wn = warp & 1;           // 0..1
    const int g  = lane >> 2, tg = lane & 3;
    const size_t e0 = (size_t)blockIdx.x * BM;
    const int ny = blockIdx.y;         // N-half
    const int n_off = ny * BN;

    if (tid < BM) s_seg[tid] = seg[e0 + tid];

    const uint32_t sbase = smem_u32(sm);

    // ---- async chunk loader: A[128x32] + B[128x32] raw fp32, padded rows ----
    auto load_chunk = [&](int kc, int stage) {
        const uint32_t ab = sbase + (uint32_t)stage * (STG_FLTS * 4);
        const uint32_t bb = ab + BM * LDT * 4;
        const int kb = kc * BK;
        #pragma unroll
        for (int t = 0; t < 4; ++t) {              // A: 1024 chunks of 16B
            int idx = tid + 256 * t;
            int row = idx >> 3, q = idx & 7;
            CP16(ab + (uint32_t)(row * LDT + q * 4) * 4,
                 h_all + (e0 + row) * HID + kb + q * 4);
        }
        #pragma unroll
        for (int t = 0; t < 4; ++t) {              // B: 1024 chunks of 16B
            int idx = tid + 256 * t;
            int row = idx >> 3, q = idx & 7;
            CP16(bb + (uint32_t)(row * LDT + q * 4) * 4,
                 W_hf + (size_t)(n_off + row) * HID + kb + q * 4);
        }
    };

    load_chunk(0, 0); CP_COMMIT();
    load_chunk(1, 1); CP_COMMIT();
    load_chunk(2, 2); CP_COMMIT();

    float acc[2][8][4];
    #pragma unroll
    for (int i = 0; i < 2; ++i)
        #pragma unroll
        for (int j = 0; j < 8; ++j)
            #pragma unroll
            for (int q = 0; q < 4; ++q) acc[i][j][q] = 0.f;

    for (int kc = 0; kc < 8; ++kc) {
        CP_WAIT2();
        __syncthreads();

        const float* As = sm + (kc % 3) * STG_FLTS;
        const float* Bs = As + BM * LDT;

        #pragma unroll
        for (int k8 = 0; k8 < 4; ++k8) {
            const int kb = k8 * 8;
            uint32_t a[2][4], b[8][2];
            #pragma unroll
            for (int i = 0; i < 2; ++i) {
                int rm = wm * 32 + i * 16;
                a[i][0] = __float_as_uint(As[(rm + g    ) * LDT + kb + tg    ]);
                a[i][1] = __float_as_uint(As[(rm + g + 8) * LDT + kb + tg    ]);
                a[i][2] = __float_as_uint(As[(rm + g    ) * LDT + kb + tg + 4]);
                a[i][3] = __float_as_uint(As[(rm + g + 8) * LDT + kb + tg + 4]);
            }
            #pragma unroll
            for (int j = 0; j < 8; ++j) {
                int cn = wn * 64 + j * 8 + g;
                b[j][0] = __float_as_uint(Bs[cn * LDT + kb + tg    ]);
                b[j][1] = __float_as_uint(Bs[cn * LDT + kb + tg + 4]);
            }
            #pragma unroll
            for (int i = 0; i < 2; ++i)
                #pragma unroll
                for (int j = 0; j < 8; ++j) {
                    asm volatile(
                        "mma.sync.aligned.m16n8k8.row.col.f32.tf32.tf32.f32 "
                        "{%0,%1,%2,%3},{%4,%5,%6,%7},{%8,%9},{%0,%1,%2,%3};"
                        : "+f"(acc[i][j][0]), "+f"(acc[i][j][1]),
                          "+f"(acc[i][j][2]), "+f"(acc[i][j][3])
                        : "r"(a[i][0]), "r"(a[i][1]), "r"(a[i][2]), "r"(a[i][3]),
                          "r"(b[j][0]), "r"(b[j][1]));
                }
        }

        __syncthreads();
        if (kc + 3 < 8) load_chunk(kc + 3, kc % 3);
        CP_COMMIT();
    }

    // ---- epilogue: stage Uh tile (transposed view) then segment-reduce ----
    float* Sm = sm;                    // [BM][132]
    #pragma unroll
    for (int i = 0; i < 2; ++i)
        #pragma unroll
        for (int j = 0; j < 8; ++j) {
            int row = wm * 32 + i * 16 + g;
            int col = wn * 64 + j * 8 + tg * 2;
            Sm[row * 132 + col]           = acc[i][j][0];
            Sm[row * 132 + col + 1]       = acc[i][j][1];
            Sm[(row + 8) * 132 + col]     = acc[i][j][2];
            Sm[(row + 8) * 132 + col + 1] = acc[i][j][3];
        }
    __syncthreads();

    const int cl    = tid & 127;                 // column within tile
    const int ebase = (tid >> 7) * 64;           // edge half
    const int col   = n_off + cl;
    const float bf  = b_f[col];

    int prev = -1;
    float accu = 0.f;
    for (int e = ebase; e < ebase + 64; ++e) {
        int node = s_seg[e];
        if (node != prev) {
            if (prev >= 0) atomicAdd(&out[(size_t)prev * HID + col], accu);
            prev = node;
            accu = 0.f;
        }
        float z = Sm[e * 132 + cl] + bf + g_Wx[(size_t)node * HID + col];
        float f = 1.0f / (1.0f + __expf(-z));
        accu += f * c_all[(e0 + e) * HID + col];
    }
    atomicAdd(&out[(size_t)prev * HID + col], accu);
}

// ---------------------------------------------------------------------------
extern "C" void kernel_launch(void* const* d_in, const int* in_sizes, int n_in,
                              void* d_out, int out_size)
{
    const float* x     = (const float*)d_in[0];
    const float* h_all = (const float*)d_in[1];
    const float* c_all = (const float*)d_in[2];
    const int*   seg   = (const int*)  d_in[3];
    const float* W_if  = (const float*)d_in[4];
    const float* W_hf  = (const float*)d_in[5];
    const float* b_f   = (const float*)d_in[6];
    float* out = (float*)d_out;

    const int smemA = (32 * NT + NT * 260) * (int)sizeof(float);   // 63072

    cudaFuncSetAttribute(wx_kernel,
        cudaFuncAttributeMaxDynamicSharedMemorySize, smemA);
    cudaFuncSetAttribute(fused_mma,
        cudaFuncAttributeMaxDynamicSharedMemorySize, SMEM_DYN);

    cudaMemsetAsync(d_out, 0, (size_t)out_size * sizeof(float));
    wx_kernel<<<N_NODES / 32, 256, smemA>>>(x, W_if);
    dim3 grid(N_EDGES / BM, HID / BN);
    fused_mma<<<grid, 256, SMEM_DYN>>>(h_all, c_all, seg, W_hf, b_f, out);
}

// round 4
// speedup vs baseline: 2.3229x; 2.0253x over previous
#include <cuda_runtime.h>
#include <cstdint>

#define N_NODES 100000
#define N_EDGES 400000
#define HID 256
#define NT 54
#define KTOT 320          // 256 (h) + 54 (x) padded to 320
#define NCHUNK 10

// ---------------------------------------------------------------------------
#define CP16(dst, src) \
    asm volatile("cp.async.cg.shared.global [%0], [%1], 16;" \
                 :: "r"(dst), "l"(src) : "memory")
#define CP8(dst, src) \
    asm volatile("cp.async.ca.shared.global [%0], [%1], 8;" \
                 :: "r"(dst), "l"(src) : "memory")
#define ZERO8(dst) \
    asm volatile("st.shared.u64 [%0], %1;" :: "r"(dst), "l"(0ULL) : "memory")
#define CP_COMMIT()  asm volatile("cp.async.commit_group;" ::: "memory")
#define CP_WAIT2()   asm volatile("cp.async.wait_group 2;" ::: "memory")

__device__ __forceinline__ uint32_t smem_u32(const void* p) {
    uint32_t a;
    asm("{ .reg .u64 t; cvta.to.shared.u64 t, %1; cvt.u32.u64 %0, t; }"
        : "=r"(a) : "l"(p));
    return a;
}

// ---------------------------------------------------------------------------
// Fused kernel: z = [h_all | x[seg]] @ [W_hf | W_if]^T   (tf32 mma.sync)
//   BM=128 edges, BN=128 cols, BK=32, 3-stage cp.async pipeline.
//   Epilogue: sigmoid(z + b_f) * c_all, run-length segment-sum, atomicAdd.
// Grid: (3125, 2). 256 threads = 8 warps, 4(m) x 2(n), warp tile 32x64.
// ---------------------------------------------------------------------------
#define BM 128
#define BN 128
#define BK 32
#define LDT 36                         // padded row pitch (floats)
#define STG_FLTS ((BM + BN) * LDT)     // 9216 floats = 36864 B
#define SMEM_DYN (3 * STG_FLTS * 4)    // 110592 B

__global__ void __launch_bounds__(256, 2) fused_mma(
    const float* __restrict__ h_all, const float* __restrict__ c_all,
    const int*   __restrict__ seg,   const float* __restrict__ W_hf,
    const float* __restrict__ b_f,   const float* __restrict__ x,
    const float* __restrict__ W_if,  float* __restrict__ out)
{
    extern __shared__ float sm[];
    __shared__ int s_seg[BM];

    const int tid  = threadIdx.x;
    const int lane = tid & 31;
    const int warp = tid >> 5;
    const int wm = warp >> 1;          // 0..3
    const int wn = warp & 1;           // 0..1
    const int g  = lane >> 2, tg = lane & 3;
    const size_t e0 = (size_t)blockIdx.x * BM;
    const int n_off = blockIdx.y * BN;

    if (tid < BM) s_seg[tid] = seg[e0 + tid];
    __syncthreads();                   // s_seg needed by tail loader

    const uint32_t sbase = smem_u32(sm);

    // ---- main chunks (kc 0..7): A rows from h_all, B rows from W_hf ----
    auto load_main = [&](int kc, int stage) {
        const uint32_t ab = sbase + (uint32_t)stage * (STG_FLTS * 4);
        const uint32_t bb = ab + BM * LDT * 4;
        const int kb = kc * BK;
        #pragma unroll
        for (int t = 0; t < 4; ++t) {
            int idx = tid + 256 * t;
            int row = idx >> 3, q = idx & 7;
            CP16(ab + (uint32_t)(row * LDT + q * 4) * 4,
                 h_all + (e0 + row) * HID + kb + q * 4);
        }
        #pragma unroll
        for (int t = 0; t < 4; ++t) {
            int idx = tid + 256 * t;
            int row = idx >> 3, q = idx & 7;
            CP16(bb + (uint32_t)(row * LDT + q * 4) * 4,
                 W_hf + (size_t)(n_off + row) * HID + kb + q * 4);
        }
    };

    // ---- tail chunks (kc 8..9): A rows gather x[seg], B rows from W_if ----
    // Source rows are 54 floats (216 B stride, 8-byte aligned): 8B cp.async.
    auto load_tail = [&](int kc, int stage) {
        const uint32_t ab = sbase + (uint32_t)stage * (STG_FLTS * 4);
        const uint32_t bb = ab + BM * LDT * 4;
        const int xc0 = (kc - 8) * BK;   // 0 or 32
        #pragma unroll
        for (int t = 0; t < 4; ++t) {
            int idx = tid + 256 * t;
            int row = idx >> 3, q = idx & 7;
            int col = xc0 + q * 4;
            uint32_t d = ab + (uint32_t)(row * LDT + q * 4) * 4;
            const float* src = x + (size_t)s_seg[row] * NT + col;
            if (col + 1 < NT) CP8(d, src);          else ZERO8(d);
            if (col + 3 < NT) CP8(d + 8, src + 2);  else ZERO8(d + 8);
        }
        #pragma unroll
        for (int t = 0; t < 4; ++t) {
            int idx = tid + 256 * t;
            int row = idx >> 3, q = idx & 7;
            int col = xc0 + q * 4;
            uint32_t d = bb + (uint32_t)(row * LDT + q * 4) * 4;
            const float* src = W_if + (size_t)(n_off + row) * NT + col;
            if (col + 1 < NT) CP8(d, src);          else ZERO8(d);
            if (col + 3 < NT) CP8(d + 8, src + 2);  else ZERO8(d + 8);
        }
    };

    load_main(0, 0); CP_COMMIT();
    load_main(1, 1); CP_COMMIT();
    load_main(2, 2); CP_COMMIT();

    float acc[2][8][4];
    #pragma unroll
    for (int i = 0; i < 2; ++i)
        #pragma unroll
        for (int j = 0; j < 8; ++j)
            #pragma unroll
            for (int q = 0; q < 4; ++q) acc[i][j][q] = 0.f;

    for (int kc = 0; kc < NCHUNK; ++kc) {
        CP_WAIT2();
        __syncthreads();

        const float* As = sm + (kc % 3) * STG_FLTS;
        const float* Bs = As + BM * LDT;

        #pragma unroll
        for (int k8 = 0; k8 < 4; ++k8) {
            const int kb = k8 * 8;
            uint32_t a[2][4], b[8][2];
            #pragma unroll
            for (int i = 0; i < 2; ++i) {
                int rm = wm * 32 + i * 16;
                a[i][0] = __float_as_uint(As[(rm + g    ) * LDT + kb + tg    ]);
                a[i][1] = __float_as_uint(As[(rm + g + 8) * LDT + kb + tg    ]);
                a[i][2] = __float_as_uint(As[(rm + g    ) * LDT + kb + tg + 4]);
                a[i][3] = __float_as_uint(As[(rm + g + 8) * LDT + kb + tg + 4]);
            }
            #pragma unroll
            for (int j = 0; j < 8; ++j) {
                int cn = wn * 64 + j * 8 + g;
                b[j][0] = __float_as_uint(Bs[cn * LDT + kb + tg    ]);
                b[j][1] = __float_as_uint(Bs[cn * LDT + kb + tg + 4]);
            }
            #pragma unroll
            for (int i = 0; i < 2; ++i)
                #pragma unroll
                for (int j = 0; j < 8; ++j) {
                    asm volatile(
                        "mma.sync.aligned.m16n8k8.row.col.f32.tf32.tf32.f32 "
                        "{%0,%1,%2,%3},{%4,%5,%6,%7},{%8,%9},{%0,%1,%2,%3};"
                        : "+f"(acc[i][j][0]), "+f"(acc[i][j][1]),
                          "+f"(acc[i][j][2]), "+f"(acc[i][j][3])
                        : "r"(a[i][0]), "r"(a[i][1]), "r"(a[i][2]), "r"(a[i][3]),
                          "r"(b[j][0]), "r"(b[j][1]));
                }
        }

        __syncthreads();
        if (kc + 3 < NCHUNK) {
            if (kc + 3 < 8) load_main(kc + 3, kc % 3);
            else            load_tail(kc + 3, kc % 3);
        }
        CP_COMMIT();
    }

    // ---- epilogue: stage z tile, then segmented sigmoid-reduce ----
    float* Sm = sm;                    // [BM][132]
    #pragma unroll
    for (int i = 0; i < 2; ++i)
        #pragma unroll
        for (int j = 0; j < 8; ++j) {
            int row = wm * 32 + i * 16 + g;
            int col = wn * 64 + j * 8 + tg * 2;
            Sm[row * 132 + col]           = acc[i][j][0];
            Sm[row * 132 + col + 1]       = acc[i][j][1];
            Sm[(row + 8) * 132 + col]     = acc[i][j][2];
            Sm[(row + 8) * 132 + col + 1] = acc[i][j][3];
        }
    __syncthreads();

    const int cl    = tid & 127;                 // column within tile
    const int ebase = (tid >> 7) * 64;           // which 64-edge half
    const int col   = n_off + cl;
    const float bf  = b_f[col];

    int prev = -1;
    float accu = 0.f;
    for (int eb = ebase; eb < ebase + 64; eb += 8) {
        float fv[8];
        #pragma unroll
        for (int u = 0; u < 8; ++u)              // batched: MLP = 8
            fv[u] = c_all[(e0 + eb + u) * HID + col];
        #pragma unroll
        for (int u = 0; u < 8; ++u) {
            float z = Sm[(eb + u) * 132 + cl] + bf;
            fv[u] *= 1.0f / (1.0f + __expf(-z));
        }
        #pragma unroll
        for (int u = 0; u < 8; ++u) {
            int node = s_seg[eb + u];
            if (node != prev) {
                if (prev >= 0) atomicAdd(&out[(size_t)prev * HID + col], accu);
                prev = node;
                accu = 0.f;
            }
            accu += fv[u];
        }
    }
    atomicAdd(&out[(size_t)prev * HID + col], accu);
}

// ---------------------------------------------------------------------------
extern "C" void kernel_launch(void* const* d_in, const int* in_sizes, int n_in,
                              void* d_out, int out_size)
{
    const float* x     = (const float*)d_in[0];
    const float* h_all = (const float*)d_in[1];
    const float* c_all = (const float*)d_in[2];
    const int*   seg   = (const int*)  d_in[3];
    const float* W_if  = (const float*)d_in[4];
    const float* W_hf  = (const float*)d_in[5];
    const float* b_f   = (const float*)d_in[6];
    float* out = (float*)d_out;

    cudaFuncSetAttribute(fused_mma,
        cudaFuncAttributeMaxDynamicSharedMemorySize, SMEM_DYN);

    cudaMemsetAsync(d_out, 0, (size_t)out_size * sizeof(float));
    dim3 grid(N_EDGES / BM, HID / BN);
    fused_mma<<<grid, 256, SMEM_DYN>>>(h_all, c_all, seg, W_hf, b_f,
                                       x, W_if, out);
}

// round 5
// speedup vs baseline: 2.4544x; 1.0566x over previous
#include <cuda_runtime.h>
#include <cstdint>

#define N_NODES 100000
#define N_EDGES 400000
#define HID 256
#define NT 54
#define NCHUNK 10

// ---------------------------------------------------------------------------
#define CP16(dst, src) \
    asm volatile("cp.async.cg.shared.global [%0], [%1], 16;" \
                 :: "r"(dst), "l"(src) : "memory")
#define CP8(dst, src) \
    asm volatile("cp.async.ca.shared.global [%0], [%1], 8;" \
                 :: "r"(dst), "l"(src) : "memory")
#define ZERO8(dst) \
    asm volatile("st.shared.u64 [%0], %1;" :: "r"(dst), "l"(0ULL) : "memory")
#define CP_COMMIT()  asm volatile("cp.async.commit_group;" ::: "memory")
#define CP_WAIT2()   asm volatile("cp.async.wait_group 2;" ::: "memory")

__device__ __forceinline__ uint32_t smem_u32(const void* p) {
    uint32_t a;
    asm("{ .reg .u64 t; cvta.to.shared.u64 t, %1; cvt.u32.u64 %0, t; }"
        : "=r"(a) : "l"(p));
    return a;
}

// ---------------------------------------------------------------------------
// Fused: z = [h_all | x[seg]] @ [W_hf | W_if]^T (tf32 mma.sync)
//   BM=128, BN=128, BK=32, 3-stage cp.async. K-permuted LDS.128 fragments:
//   thread tg holds k=4tg..4tg+3 of each 16-wide window; each window feeds
//   2 MMAs with pairs (f0,f1),(f2,f3). Valid since A,B use same k-order.
//   Swizzle: 16B chunk q of row r stored at q ^ ((r&1)<<2)  -> conflict-free.
// Epilogue: sigmoid(z+b_f)*c_all, run-length segment-sum, atomicAdd.
// ---------------------------------------------------------------------------
#define BM 128
#define BN 128
#define STG_BYTES 32768                // A 128x128B + B 128x128B
#define STG_FLTS  8192
#define SMEM_DYN  (3 * STG_BYTES)      // 98304

__global__ void __launch_bounds__(256, 2) fused_mma(
    const float* __restrict__ h_all, const float* __restrict__ c_all,
    const int*   __restrict__ seg,   const float* __restrict__ W_hf,
    const float* __restrict__ b_f,   const float* __restrict__ x,
    const float* __restrict__ W_if,  float* __restrict__ out)
{
    extern __shared__ float sm[];
    __shared__ int s_seg[BM];

    const int tid  = threadIdx.x;
    const int lane = tid & 31;
    const int warp = tid >> 5;
    const int wm = warp >> 1;          // 0..3
    const int wn = warp & 1;           // 0..1
    const int g  = lane >> 2, tg = lane & 3;
    const size_t e0 = (size_t)blockIdx.x * BM;
    const int n_off = blockIdx.y * BN;

    if (tid < BM) s_seg[tid] = seg[e0 + tid];
    __syncthreads();

    const uint32_t sbase = smem_u32(sm);

    // physical 16B-chunk position for logical chunk q of row r
    auto phys = [](int q, int r) { return q ^ ((r & 1) << 2); };

    // ---- main chunks (kc 0..7): A from h_all, B from W_hf ----
    auto load_main = [&](int kc, int stage) {
        const uint32_t ab = sbase + (uint32_t)stage * STG_BYTES;
        const uint32_t bb = ab + BM * 128;
        const int kb = kc * 32;
        #pragma unroll
        for (int t = 0; t < 4; ++t) {
            int idx = tid + 256 * t;
            int row = idx >> 3, q = idx & 7;
            CP16(ab + (uint32_t)(row * 128 + (phys(q, row) << 4)),
                 h_all + (e0 + row) * HID + kb + q * 4);
        }
        #pragma unroll
        for (int t = 0; t < 4; ++t) {
            int idx = tid + 256 * t;
            int row = idx >> 3, q = idx & 7;
            CP16(bb + (uint32_t)(row * 128 + (phys(q, row) << 4)),
                 W_hf + (size_t)(n_off + row) * HID + kb + q * 4);
        }
    };

    // ---- tail chunks (kc 8..9): A gathers x[seg], B from W_if ----
    auto load_tail = [&](int kc, int stage) {
        const uint32_t ab = sbase + (uint32_t)stage * STG_BYTES;
        const uint32_t bb = ab + BM * 128;
        const int xc0 = (kc - 8) * 32;
        #pragma unroll
        for (int t = 0; t < 4; ++t) {
            int idx = tid + 256 * t;
            int row = idx >> 3, q = idx & 7;
            int col = xc0 + q * 4;
            uint32_t d = ab + (uint32_t)(row * 128 + (phys(q, row) << 4));
            const float* src = x + (size_t)s_seg[row] * NT + col;
            if (col + 1 < NT) CP8(d, src);          else ZERO8(d);
            if (col + 3 < NT) CP8(d + 8, src + 2);  else ZERO8(d + 8);
        }
        #pragma unroll
        for (int t = 0; t < 4; ++t) {
            int idx = tid + 256 * t;
            int row = idx >> 3, q = idx & 7;
            int col = xc0 + q * 4;
            uint32_t d = bb + (uint32_t)(row * 128 + (phys(q, row) << 4));
            const float* src = W_if + (size_t)(n_off + row) * NT + col;
            if (col + 1 < NT) CP8(d, src);          else ZERO8(d);
            if (col + 3 < NT) CP8(d + 8, src + 2);  else ZERO8(d + 8);
        }
    };

    load_main(0, 0); CP_COMMIT();
    load_main(1, 1); CP_COMMIT();
    load_main(2, 2); CP_COMMIT();

    float acc[2][8][4];
    #pragma unroll
    for (int i = 0; i < 2; ++i)
        #pragma unroll
        for (int j = 0; j < 8; ++j)
            #pragma unroll
            for (int q = 0; q < 4; ++q) acc[i][j][q] = 0.f;

    const int psw = (g & 1) << 2;      // per-thread chunk swizzle bit

    for (int kc = 0; kc < NCHUNK; ++kc) {
        CP_WAIT2();
        __syncthreads();

        const float* As = sm + (kc % 3) * STG_FLTS;
        const float* Bs = As + BM * 32;

        #pragma unroll
        for (int w = 0; w < 2; ++w) {          // two 16-wide k windows
            const int p = ((w * 4) ^ psw) + tg;  // physical chunk
            float4 alo[2], ahi[2], bv[8];
            #pragma unroll
            for (int i = 0; i < 2; ++i) {
                int r = wm * 32 + i * 16 + g;
                alo[i] = *reinterpret_cast<const float4*>(As + r * 32 + p * 4);
                ahi[i] = *reinterpret_cast<const float4*>(As + (r + 8) * 32 + p * 4);
            }
            #pragma unroll
            for (int j = 0; j < 8; ++j) {
                int cn = wn * 64 + j * 8 + g;
                bv[j] = *reinterpret_cast<const float4*>(Bs + cn * 32 + p * 4);
            }
            #pragma unroll
            for (int mk = 0; mk < 2; ++mk) {   // two MMAs per window
                #pragma unroll
                for (int i = 0; i < 2; ++i) {
                    uint32_t a0 = __float_as_uint(mk ? alo[i].z : alo[i].x);
                    uint32_t a1 = __float_as_uint(mk ? ahi[i].z : ahi[i].x);
                    uint32_t a2 = __float_as_uint(mk ? alo[i].w : alo[i].y);
                    uint32_t a3 = __float_as_uint(mk ? ahi[i].w : ahi[i].y);
                    #pragma unroll
                    for (int j = 0; j < 8; ++j) {
                        uint32_t b0 = __float_as_uint(mk ? bv[j].z : bv[j].x);
                        uint32_t b1 = __float_as_uint(mk ? bv[j].w : bv[j].y);
                        asm volatile(
                            "mma.sync.aligned.m16n8k8.row.col.f32.tf32.tf32.f32 "
                            "{%0,%1,%2,%3},{%4,%5,%6,%7},{%8,%9},{%0,%1,%2,%3};"
                            : "+f"(acc[i][j][0]), "+f"(acc[i][j][1]),
                              "+f"(acc[i][j][2]), "+f"(acc[i][j][3])
                            : "r"(a0), "r"(a1), "r"(a2), "r"(a3),
                              "r"(b0), "r"(b1));
                    }
                }
            }
        }

        __syncthreads();
        if (kc + 3 < NCHUNK) {
            if (kc + 3 < 8) load_main(kc + 3, kc % 3);
            else            load_tail(kc + 3, kc % 3);
        }
        CP_COMMIT();
    }

    // ---- epilogue: stage z tile, then segmented sigmoid-reduce ----
    float* Sm = sm;                    // [BM][132]
    #pragma unroll
    for (int i = 0; i < 2; ++i)
        #pragma unroll
        for (int j = 0; j < 8; ++j) {
            int row = wm * 32 + i * 16 + g;
            int col = wn * 64 + j * 8 + tg * 2;
            Sm[row * 132 + col]           = acc[i][j][0];
            Sm[row * 132 + col + 1]       = acc[i][j][1];
            Sm[(row + 8) * 132 + col]     = acc[i][j][2];
            Sm[(row + 8) * 132 + col + 1] = acc[i][j][3];
        }
    __syncthreads();

    const int cl    = tid & 127;
    const int ebase = (tid >> 7) * 64;
    const int col   = n_off + cl;
    const float bf  = b_f[col];

    float fv[8];
    #pragma unroll
    for (int u = 0; u < 8; ++u)
        fv[u] = c_all[(e0 + ebase + u) * HID + col];

    int prev = -1;
    float accu = 0.f;
    for (int eb = ebase; eb < ebase + 64; eb += 8) {
        float nx[8];
        if (eb + 8 < ebase + 64) {
            #pragma unroll
            for (int u = 0; u < 8; ++u)          // prefetch next batch, MLP=8
                nx[u] = c_all[(e0 + eb + 8 + u) * HID + col];
        }
        #pragma unroll
        for (int u = 0; u < 8; ++u) {
            float z = Sm[(eb + u) * 132 + cl] + bf;
            fv[u] *= 1.0f / (1.0f + __expf(-z));
        }
        #pragma unroll
        for (int u = 0; u < 8; ++u) {
            int node = s_seg[eb + u];
            if (node != prev) {
                if (prev >= 0) atomicAdd(&out[(size_t)prev * HID + col], accu);
                prev = node;
                accu = 0.f;
            }
            accu += fv[u];
        }
        #pragma unroll
        for (int u = 0; u < 8; ++u) fv[u] = nx[u];
    }
    atomicAdd(&out[(size_t)prev * HID + col], accu);
}

// ---------------------------------------------------------------------------
extern "C" void kernel_launch(void* const* d_in, const int* in_sizes, int n_in,
                              void* d_out, int out_size)
{
    const float* x     = (const float*)d_in[0];
    const float* h_all = (const float*)d_in[1];
    const float* c_all = (const float*)d_in[2];
    const int*   seg   = (const int*)  d_in[3];
    const float* W_if  = (const float*)d_in[4];
    const float* W_hf  = (const float*)d_in[5];
    const float* b_f   = (const float*)d_in[6];
    float* out = (float*)d_out;

    cudaFuncSetAttribute(fused_mma,
        cudaFuncAttributeMaxDynamicSharedMemorySize, SMEM_DYN);

    cudaMemsetAsync(d_out, 0, (size_t)out_size * sizeof(float));
    dim3 grid(N_EDGES / BM, HID / BN);
    fused_mma<<<grid, 256, SMEM_DYN>>>(h_all, c_all, seg, W_hf, b_f,
                                       x, W_if, out);
}

// round 6
// speedup vs baseline: 2.7209x; 1.1086x over previous
#include <cuda_runtime.h>
#include <cuda_fp16.h>
#include <cstdint>

#define N_NODES 100000
#define N_EDGES 400000
#define HID 256
#define NT 54
#define XP 64            // x padded width (halves)
#define KW 320           // combined W width: 256 (W_hf) + 54 (W_if) + 10 pad
#define NCHUNK 5         // 5 x 64-k chunks
#define BM 128
#define BN 256
#define STG_HALVES 24576          // (BM+BN)*64
#define STG_BYTES  49152
#define SMEM_DYN   (3 * STG_BYTES)  // 147456

// fp16 staging of inputs (device globals: allocation-free scratch)
__device__ __half g_h16[(size_t)N_EDGES * HID];   // 204.8 MB
__device__ __half g_x16[(size_t)N_NODES * XP];    // 12.8 MB (zero-padded)
__device__ __half g_Wc [(size_t)HID * KW];        // 160 KB  [W_hf | W_if | 0]

// ---------------------------------------------------------------------------
#define CP16(dst, src) \
    asm volatile("cp.async.cg.shared.global [%0], [%1], 16;" \
                 :: "r"(dst), "l"(src) : "memory")
#define CP_COMMIT()  asm volatile("cp.async.commit_group;" ::: "memory")
#define CP_WAIT2()   asm volatile("cp.async.wait_group 2;" ::: "memory")

__device__ __forceinline__ uint32_t smem_u32(const void* p) {
    uint32_t a;
    asm("{ .reg .u64 t; cvta.to.shared.u64 t, %1; cvt.u32.u64 %0, t; }"
        : "=r"(a) : "l"(p));
    return a;
}

// ---------------------------------------------------------------------------
// Conversion kernels (one-time, streamed)
// ---------------------------------------------------------------------------
__global__ void __launch_bounds__(256) cvt_h(const float* __restrict__ h)
{
    const size_t n = (size_t)N_EDGES * HID / 8;
    const size_t stride = (size_t)gridDim.x * blockDim.x;
    const float4* src = reinterpret_cast<const float4*>(h);
    uint4* dst = reinterpret_cast<uint4*>(g_h16);
    for (size_t i = (size_t)blockIdx.x * blockDim.x + threadIdx.x;
         i < n; i += stride) {
        float4 a = src[2 * i], b = src[2 * i + 1];
        __half2 p0 = __floats2half2_rn(a.x, a.y);
        __half2 p1 = __floats2half2_rn(a.z, a.w);
        __half2 p2 = __floats2half2_rn(b.x, b.y);
        __half2 p3 = __floats2half2_rn(b.z, b.w);
        uint4 o;
        o.x = *reinterpret_cast<uint32_t*>(&p0);
        o.y = *reinterpret_cast<uint32_t*>(&p1);
        o.z = *reinterpret_cast<uint32_t*>(&p2);
        o.w = *reinterpret_cast<uint32_t*>(&p3);
        dst[i] = o;
    }
}

__global__ void __launch_bounds__(256) cvt_x(const float* __restrict__ x)
{
    const size_t n = (size_t)N_NODES * XP;
    const size_t stride = (size_t)gridDim.x * blockDim.x;
    for (size_t i = (size_t)blockIdx.x * blockDim.x + threadIdx.x;
         i < n; i += stride) {
        size_t row = i >> 6;
        int c = (int)(i & 63);
        float v = (c < NT) ? x[row * NT + c] : 0.0f;
        g_x16[i] = __float2half_rn(v);
    }
}

__global__ void __launch_bounds__(256) cvt_w(const float* __restrict__ W_hf,
                                             const float* __restrict__ W_if)
{
    const int n = HID * KW;   // 81920
    for (int i = blockIdx.x * blockDim.x + threadIdx.x;
         i < n; i += gridDim.x * blockDim.x) {
        int row = i / KW, c = i % KW;
        float v = 0.0f;
        if (c < HID)            v = W_hf[row * HID + c];
        else if (c < HID + NT)  v = W_if[row * NT + (c - HID)];
        g_Wc[i] = __float2half_rn(v);
    }
}

// ---------------------------------------------------------------------------
// Fused fp16 GEMM + epilogue.
//   z[128 e x 256 h] = [h16 | x16[seg]] @ [Wc]^T, K=320, BK=64, 3-stage.
//   m16n8k16 MMAs; thread tg owns 8 contiguous halves per 32-k window-pair
//   (one LDS.128), feeding two MMAs (.x/.y then .z/.w). A,B identically
//   k-permuted -> result exact. Swizzle: chunk p stored at p^((row&1)<<2).
//   Epilogue: sigmoid(z+b_f)*c_all, run-length segment-sum, atomicAdd.
// 512 threads = 16 warps, 4(m) x 4(n); warp tile 32 x 64.
// ---------------------------------------------------------------------------
__global__ void __launch_bounds__(512, 1) fused_mma(
    const float* __restrict__ c_all, const int* __restrict__ seg,
    const float* __restrict__ b_f,   float* __restrict__ out)
{
    extern __shared__ __half smh[];
    __shared__ int s_seg[BM];

    const int tid  = threadIdx.x;
    const int lane = tid & 31;
    const int warp = tid >> 5;
    const int wm = warp >> 2;          // 0..3
    const int wn = warp & 3;           // 0..3
    const int g  = lane >> 2, tg = lane & 3;
    const size_t e0 = (size_t)blockIdx.x * BM;

    if (tid < BM) s_seg[tid] = seg[e0 + tid];
    __syncthreads();

    const uint32_t sbase = smem_u32(smh);

    // loader: A 128x64h (1024 16B chunks), B 256x64h (2048 chunks)
    auto load_chunk = [&](int kc, int stage) {
        const uint32_t ab = sbase + (uint32_t)stage * STG_BYTES;
        const uint32_t bb = ab + BM * 128;
        #pragma unroll
        for (int t = 0; t < 2; ++t) {
            int idx = tid + 512 * t;
            int row = idx >> 3, q = idx & 7;
            uint32_t d = ab + (uint32_t)(row * 128 + ((q ^ ((row & 1) << 2)) << 4));
            const __half* src = (kc < 4)
                ? g_h16 + (e0 + row) * HID + kc * 64 + q * 8
                : g_x16 + (size_t)s_seg[row] * XP + q * 8;
            CP16(d, src);
        }
        #pragma unroll
        for (int t = 0; t < 4; ++t) {
            int idx = tid + 512 * t;
            int row = idx >> 3, q = idx & 7;
            uint32_t d = bb + (uint32_t)(row * 128 + ((q ^ ((row & 1) << 2)) << 4));
            CP16(d, g_Wc + (size_t)row * KW + kc * 64 + q * 8);
        }
    };

    load_chunk(0, 0); CP_COMMIT();
    load_chunk(1, 1); CP_COMMIT();
    load_chunk(2, 2); CP_COMMIT();

    float acc[2][8][4];
    #pragma unroll
    for (int i = 0; i < 2; ++i)
        #pragma unroll
        for (int j = 0; j < 8; ++j)
            #pragma unroll
            for (int q = 0; q < 4; ++q) acc[i][j][q] = 0.f;

    const int psw = (g & 1) << 2;      // parity swizzle (rows used have parity g&1)

    for (int kc = 0; kc < NCHUNK; ++kc) {
        CP_WAIT2();
        __syncthreads();

        const __half* Sa = smh + (kc % 3) * STG_HALVES;
        const __half* Sb = Sa + BM * 64;

        #pragma unroll
        for (int wp = 0; wp < 2; ++wp) {       // two 32-k window pairs
            const int pc = (wp * 4 + tg) ^ psw;  // physical 16B chunk
            uint4 alo[2], ahi[2], bv[8];
            #pragma unroll
            for (int i = 0; i < 2; ++i) {
                int r = wm * 32 + i * 16 + g;
                alo[i] = *reinterpret_cast<const uint4*>(Sa + r * 64 + pc * 8);
                ahi[i] = *reinterpret_cast<const uint4*>(Sa + (r + 8) * 64 + pc * 8);
            }
            #pragma unroll
            for (int j = 0; j < 8; ++j) {
                int cn = wn * 64 + j * 8 + g;
                bv[j] = *reinterpret_cast<const uint4*>(Sb + cn * 64 + pc * 8);
            }
            #pragma unroll
            for (int s = 0; s < 2; ++s) {      // two k16 MMAs per pair
                #pragma unroll
                for (int i = 0; i < 2; ++i) {
                    uint32_t a0 = s ? alo[i].z : alo[i].x;
                    uint32_t a1 = s ? ahi[i].z : ahi[i].x;
                    uint32_t a2 = s ? alo[i].w : alo[i].y;
                    uint32_t a3 = s ? ahi[i].w : ahi[i].y;
                    #pragma unroll
                    for (int j = 0; j < 8; ++j) {
                        uint32_t b0 = s ? bv[j].z : bv[j].x;
                        uint32_t b1 = s ? bv[j].w : bv[j].y;
                        asm volatile(
                            "mma.sync.aligned.m16n8k16.row.col.f32.f16.f16.f32 "
                            "{%0,%1,%2,%3},{%4,%5,%6,%7},{%8,%9},{%0,%1,%2,%3};"
                            : "+f"(acc[i][j][0]), "+f"(acc[i][j][1]),
                              "+f"(acc[i][j][2]), "+f"(acc[i][j][3])
                            : "r"(a0), "r"(a1), "r"(a2), "r"(a3),
                              "r"(b0), "r"(b1));
                    }
                }
            }
        }

        __syncthreads();
        if (kc + 3 < NCHUNK) load_chunk(kc + 3, kc % 3);
        CP_COMMIT();
    }

    // ---- epilogue: stage full z tile [128][264], then segmented reduce ----
    float* Sm = reinterpret_cast<float*>(smh);
    #pragma unroll
    for (int i = 0; i < 2; ++i)
        #pragma unroll
        for (int j = 0; j < 8; ++j) {
            int row = wm * 32 + i * 16 + g;
            int col = wn * 64 + j * 8 + tg * 2;
            Sm[row * 264 + col]           = acc[i][j][0];
            Sm[row * 264 + col + 1]       = acc[i][j][1];
            Sm[(row + 8) * 264 + col]     = acc[i][j][2];
            Sm[(row + 8) * 264 + col + 1] = acc[i][j][3];
        }
    __syncthreads();

    const int col   = tid & 255;
    const int ebase = (tid >> 8) * 64;
    const float bf  = b_f[col];

    float fv[8];
    #pragma unroll
    for (int u = 0; u < 8; ++u)
        fv[u] = c_all[(e0 + ebase + u) * HID + col];

    int prev = -1;
    float accu = 0.f;
    for (int eb = ebase; eb < ebase + 64; eb += 8) {
        float nx[8];
        if (eb + 8 < ebase + 64) {
            #pragma unroll
            for (int u = 0; u < 8; ++u)
                nx[u] = c_all[(e0 + eb + 8 + u) * HID + col];
        }
        #pragma unroll
        for (int u = 0; u < 8; ++u) {
            float z = Sm[(eb + u) * 264 + col] + bf;
            fv[u] *= 1.0f / (1.0f + __expf(-z));
        }
        #pragma unroll
        for (int u = 0; u < 8; ++u) {
            int node = s_seg[eb + u];
            if (node != prev) {
                if (prev >= 0) atomicAdd(&out[(size_t)prev * HID + col], accu);
                prev = node;
                accu = 0.f;
            }
            accu += fv[u];
        }
        #pragma unroll
        for (int u = 0; u < 8; ++u) fv[u] = nx[u];
    }
    atomicAdd(&out[(size_t)prev * HID + col], accu);
}

// ---------------------------------------------------------------------------
extern "C" void kernel_launch(void* const* d_in, const int* in_sizes, int n_in,
                              void* d_out, int out_size)
{
    const float* x     = (const float*)d_in[0];
    const float* h_all = (const float*)d_in[1];
    const float* c_all = (const float*)d_in[2];
    const int*   seg   = (const int*)  d_in[3];
    const float* W_if  = (const float*)d_in[4];
    const float* W_hf  = (const float*)d_in[5];
    const float* b_f   = (const float*)d_in[6];
    float* out = (float*)d_out;

    cudaFuncSetAttribute(fused_mma,
        cudaFuncAttributeMaxDynamicSharedMemorySize, SMEM_DYN);

    cudaMemsetAsync(d_out, 0, (size_t)out_size * sizeof(float));
    cvt_h<<<8192, 256>>>(h_all);
    cvt_x<<<4096, 256>>>(x);
    cvt_w<<<160, 256>>>(W_hf, W_if);
    fused_mma<<<N_EDGES / BM, 512, SMEM_DYN>>>(c_all, seg, b_f, out);
}

// round 7
// speedup vs baseline: 2.8774x; 1.0575x over previous
#include <cuda_runtime.h>
#include <cuda_fp16.h>
#include <cstdint>

#define N_NODES 100000
#define N_EDGES 400000
#define HID 256
#define NT 54
#define XP 64            // x padded width (halves)
#define KW 320           // combined W width: 256 (W_hf) + 54 (W_if) + 10 pad
#define NCHUNK 5         // 5 x 64-k chunks
#define BM 128
#define BN 128
#define STG_HALVES 16384           // (BM+BN)*64
#define STG_BYTES  32768
#define SMEM_DYN   (3 * STG_BYTES)   // 98304 -> 2 CTAs/SM (192KB)

// fp16 staging of inputs (device globals: allocation-free scratch)
__device__ __half g_h16[(size_t)N_EDGES * HID];   // 204.8 MB
__device__ __half g_x16[(size_t)N_NODES * XP];    // 12.8 MB (zero-padded)
__device__ __half g_Wc [(size_t)HID * KW];        // 160 KB  [W_hf | W_if | 0]

// ---------------------------------------------------------------------------
#define CP16(dst, src) \
    asm volatile("cp.async.cg.shared.global [%0], [%1], 16;" \
                 :: "r"(dst), "l"(src) : "memory")
#define CP_COMMIT()  asm volatile("cp.async.commit_group;" ::: "memory")
#define CP_WAIT2()   asm volatile("cp.async.wait_group 2;" ::: "memory")

__device__ __forceinline__ uint32_t smem_u32(const void* p) {
    uint32_t a;
    asm("{ .reg .u64 t; cvta.to.shared.u64 t, %1; cvt.u32.u64 %0, t; }"
        : "=r"(a) : "l"(p));
    return a;
}

// ---------------------------------------------------------------------------
// Conversion kernels (one-time, streamed)
// ---------------------------------------------------------------------------
__global__ void __launch_bounds__(256) cvt_h(const float* __restrict__ h)
{
    const size_t n = (size_t)N_EDGES * HID / 8;
    const size_t stride = (size_t)gridDim.x * blockDim.x;
    const float4* src = reinterpret_cast<const float4*>(h);
    uint4* dst = reinterpret_cast<uint4*>(g_h16);
    for (size_t i = (size_t)blockIdx.x * blockDim.x + threadIdx.x;
         i < n; i += stride) {
        float4 a = src[2 * i], b = src[2 * i + 1];
        __half2 p0 = __floats2half2_rn(a.x, a.y);
        __half2 p1 = __floats2half2_rn(a.z, a.w);
        __half2 p2 = __floats2half2_rn(b.x, b.y);
        __half2 p3 = __floats2half2_rn(b.z, b.w);
        uint4 o;
        o.x = *reinterpret_cast<uint32_t*>(&p0);
        o.y = *reinterpret_cast<uint32_t*>(&p1);
        o.z = *reinterpret_cast<uint32_t*>(&p2);
        o.w = *reinterpret_cast<uint32_t*>(&p3);
        dst[i] = o;
    }
}

__global__ void __launch_bounds__(256) cvt_x(const float* __restrict__ x)
{
    const size_t n = (size_t)N_NODES * XP;
    const size_t stride = (size_t)gridDim.x * blockDim.x;
    for (size_t i = (size_t)blockIdx.x * blockDim.x + threadIdx.x;
         i < n; i += stride) {
        size_t row = i >> 6;
        int c = (int)(i & 63);
        float v = (c < NT) ? x[row * NT + c] : 0.0f;
        g_x16[i] = __float2half_rn(v);
    }
}

__global__ void __launch_bounds__(256) cvt_w(const float* __restrict__ W_hf,
                                             const float* __restrict__ W_if)
{
    const int n = HID * KW;   // 81920
    for (int i = blockIdx.x * blockDim.x + threadIdx.x;
         i < n; i += gridDim.x * blockDim.x) {
        int row = i / KW, c = i % KW;
        float v = 0.0f;
        if (c < HID)            v = W_hf[row * HID + c];
        else if (c < HID + NT)  v = W_if[row * NT + (c - HID)];
        g_Wc[i] = __float2half_rn(v);
    }
}

// ---------------------------------------------------------------------------
// Fused fp16 GEMM + epilogue.  BM=128, BN=128, BK=64, 3-stage cp.async.
//   z = [h16 | x16[seg]] @ Wc^T (K=320).  m16n8k16 MMAs; thread tg owns 8
//   contiguous halves per 32-k window pair (one LDS.128) feeding two MMAs
//   (.x/.y then .z/.w) -- A,B identically k-permuted so result is exact.
//   Swizzle: chunk q of row r stored at q ^ ((r&1)<<2) -> conflict-free.
//   Epilogue: sigmoid(z+b_f)*c_all, run-length segment-sum, atomicAdd.
// 256 threads = 8 warps, 4(m) x 2(n), warp tile 32x64. 2 CTAs/SM.
// ---------------------------------------------------------------------------
__global__ void __launch_bounds__(256, 2) fused_mma(
    const float* __restrict__ c_all, const int* __restrict__ seg,
    const float* __restrict__ b_f,   float* __restrict__ out)
{
    extern __shared__ __half smh[];
    __shared__ int s_seg[BM];

    const int tid  = threadIdx.x;
    const int lane = tid & 31;
    const int warp = tid >> 5;
    const int wm = warp >> 1;          // 0..3
    const int wn = warp & 1;           // 0..1
    const int g  = lane >> 2, tg = lane & 3;
    const size_t e0 = (size_t)blockIdx.x * BM;
    const int n_off = blockIdx.y * BN;

    if (tid < BM) s_seg[tid] = seg[e0 + tid];
    __syncthreads();

    const uint32_t sbase = smem_u32(smh);

    // loader: A 128x64h (1024 16B chunks), B 128x64h (1024 chunks)
    auto load_chunk = [&](int kc, int stage) {
        const uint32_t ab = sbase + (uint32_t)stage * STG_BYTES;
        const uint32_t bb = ab + BM * 128;
        #pragma unroll
        for (int t = 0; t < 4; ++t) {
            int idx = tid + 256 * t;
            int row = idx >> 3, q = idx & 7;
            uint32_t d = ab + (uint32_t)(row * 128 + ((q ^ ((row & 1) << 2)) << 4));
            const __half* src = (kc < 4)
                ? g_h16 + (e0 + row) * HID + kc * 64 + q * 8
                : g_x16 + (size_t)s_seg[row] * XP + q * 8;
            CP16(d, src);
        }
        #pragma unroll
        for (int t = 0; t < 4; ++t) {
            int idx = tid + 256 * t;
            int row = idx >> 3, q = idx & 7;
            uint32_t d = bb + (uint32_t)(row * 128 + ((q ^ ((row & 1) << 2)) << 4));
            CP16(d, g_Wc + (size_t)(n_off + row) * KW + kc * 64 + q * 8);
        }
    };

    load_chunk(0, 0); CP_COMMIT();
    load_chunk(1, 1); CP_COMMIT();
    load_chunk(2, 2); CP_COMMIT();

    float acc[2][8][4];
    #pragma unroll
    for (int i = 0; i < 2; ++i)
        #pragma unroll
        for (int j = 0; j < 8; ++j)
            #pragma unroll
            for (int q = 0; q < 4; ++q) acc[i][j][q] = 0.f;

    const int psw = (g & 1) << 2;      // parity swizzle (used rows have parity g&1)

    for (int kc = 0; kc < NCHUNK; ++kc) {
        CP_WAIT2();
        __syncthreads();

        const __half* Sa = smh + (kc % 3) * STG_HALVES;
        const __half* Sb = Sa + BM * 64;

        #pragma unroll
        for (int wp = 0; wp < 2; ++wp) {       // two 32-k window pairs
            const int pc = (wp * 4 + tg) ^ psw;  // physical 16B chunk
            uint4 alo[2], ahi[2], bv[8];
            #pragma unroll
            for (int i = 0; i < 2; ++i) {
                int r = wm * 32 + i * 16 + g;
                alo[i] = *reinterpret_cast<const uint4*>(Sa + r * 64 + pc * 8);
                ahi[i] = *reinterpret_cast<const uint4*>(Sa + (r + 8) * 64 + pc * 8);
            }
            #pragma unroll
            for (int j = 0; j < 8; ++j) {
                int cn = wn * 64 + j * 8 + g;
                bv[j] = *reinterpret_cast<const uint4*>(Sb + cn * 64 + pc * 8);
            }
            #pragma unroll
            for (int s = 0; s < 2; ++s) {      // two k16 MMAs per pair
                #pragma unroll
                for (int i = 0; i < 2; ++i) {
                    uint32_t a0 = s ? alo[i].z : alo[i].x;
                    uint32_t a1 = s ? ahi[i].z : ahi[i].x;
                    uint32_t a2 = s ? alo[i].w : alo[i].y;
                    uint32_t a3 = s ? ahi[i].w : ahi[i].y;
                    #pragma unroll
                    for (int j = 0; j < 8; ++j) {
                        uint32_t b0 = s ? bv[j].z : bv[j].x;
                        uint32_t b1 = s ? bv[j].w : bv[j].y;
                        asm volatile(
                            "mma.sync.aligned.m16n8k16.row.col.f32.f16.f16.f32 "
                            "{%0,%1,%2,%3},{%4,%5,%6,%7},{%8,%9},{%0,%1,%2,%3};"
                            : "+f"(acc[i][j][0]), "+f"(acc[i][j][1]),
                              "+f"(acc[i][j][2]), "+f"(acc[i][j][3])
                            : "r"(a0), "r"(a1), "r"(a2), "r"(a3),
                              "r"(b0), "r"(b1));
                    }
                }
            }
        }

        __syncthreads();
        if (kc + 3 < NCHUNK) load_chunk(kc + 3, kc % 3);
        CP_COMMIT();
    }

    // ---- epilogue: stage z tile [128][132], then segmented reduce ----
    float* Sm = reinterpret_cast<float*>(smh);
    #pragma unroll
    for (int i = 0; i < 2; ++i)
        #pragma unroll
        for (int j = 0; j < 8; ++j) {
            int row = wm * 32 + i * 16 + g;
            int col = wn * 64 + j * 8 + tg * 2;
            Sm[row * 132 + col]           = acc[i][j][0];
            Sm[row * 132 + col + 1]       = acc[i][j][1];
            Sm[(row + 8) * 132 + col]     = acc[i][j][2];
            Sm[(row + 8) * 132 + col + 1] = acc[i][j][3];
        }
    __syncthreads();

    const int cl    = tid & 127;
    const int ebase = (tid >> 7) * 64;
    const int col   = n_off + cl;
    const float bf  = b_f[col];

    float fv[8];
    #pragma unroll
    for (int u = 0; u < 8; ++u)
        fv[u] = c_all[(e0 + ebase + u) * HID + col];

    int prev = -1;
    float accu = 0.f;
    for (int eb = ebase; eb < ebase + 64; eb += 8) {
        float nx[8];
        if (eb + 8 < ebase + 64) {
            #pragma unroll
            for (int u = 0; u < 8; ++u)          // prefetch next batch, MLP=8
                nx[u] = c_all[(e0 + eb + 8 + u) * HID + col];
        }
        #pragma unroll
        for (int u = 0; u < 8; ++u) {
            float z = Sm[(eb + u) * 132 + cl] + bf;
            fv[u] *= 1.0f / (1.0f + __expf(-z));
        }
        #pragma unroll
        for (int u = 0; u < 8; ++u) {
            int node = s_seg[eb + u];
            if (node != prev) {
                if (prev >= 0) atomicAdd(&out[(size_t)prev * HID + col], accu);
                prev = node;
                accu = 0.f;
            }
            accu += fv[u];
        }
        #pragma unroll
        for (int u = 0; u < 8; ++u) fv[u] = nx[u];
    }
    atomicAdd(&out[(size_t)prev * HID + col], accu);
}

// ---------------------------------------------------------------------------
extern "C" void kernel_launch(void* const* d_in, const int* in_sizes, int n_in,
                              void* d_out, int out_size)
{
    const float* x     = (const float*)d_in[0];
    const float* h_all = (const float*)d_in[1];
    const float* c_all = (const float*)d_in[2];
    const int*   seg   = (const int*)  d_in[3];
    const float* W_if  = (const float*)d_in[4];
    const float* W_hf  = (const float*)d_in[5];
    const float* b_f   = (const float*)d_in[6];
    float* out = (float*)d_out;

    cudaFuncSetAttribute(fused_mma,
        cudaFuncAttributeMaxDynamicSharedMemorySize, SMEM_DYN);

    cudaMemsetAsync(d_out, 0, (size_t)out_size * sizeof(float));
    cvt_h<<<8192, 256>>>(h_all);
    cvt_x<<<4096, 256>>>(x);
    cvt_w<<<160, 256>>>(W_hf, W_if);
    dim3 grid(N_EDGES / BM, HID / BN);
    fused_mma<<<grid, 256, SMEM_DYN>>>(c_all, seg, b_f, out);
}

// round 8
// speedup vs baseline: 4.1836x; 1.4539x over previous
#include <cuda_runtime.h>
#include <cuda_fp16.h>
#include <cstdint>

#define N_NODES 100000
#define N_EDGES 400000
#define HID 256
#define NT 54
#define XP 64            // x padded width (floats)
#define KW 320           // combined W width: 256 (W_hf) + 54 (W_if) + 10 pad
#define NCHUNK 5         // 5 x 64-k chunks
#define BM 128
#define BN 128
#define A_STG_B 32768    // 128 rows x 64 fp32
#define B_STG_B 16384    // 128 rows x 64 fp16
#define STG_BYTES (A_STG_B + B_STG_B)      // 49152
#define SMEM_DYN  (2 * STG_BYTES)          // 98304 -> 2 CTAs/SM

// device-global scratch (allocation-free)
__device__ float  g_x32[(size_t)N_NODES * XP];    // 25.6 MB, zero-padded x
__device__ __half g_Wc [(size_t)HID * KW];        // 160 KB  [W_hf | W_if | 0]

// ---------------------------------------------------------------------------
#define CP16(dst, src) \
    asm volatile("cp.async.cg.shared.global [%0], [%1], 16;" \
                 :: "r"(dst), "l"(src) : "memory")
#define CP_COMMIT()  asm volatile("cp.async.commit_group;" ::: "memory")
#define CP_WAIT1()   asm volatile("cp.async.wait_group 1;" ::: "memory")

__device__ __forceinline__ uint32_t smem_u32(const void* p) {
    uint32_t a;
    asm("{ .reg .u64 t; cvta.to.shared.u64 t, %1; cvt.u32.u64 %0, t; }"
        : "=r"(a) : "l"(p));
    return a;
}

__device__ __forceinline__ uint32_t packh2(float a, float b) {
    __half2 h = __floats2half2_rn(a, b);
    return *reinterpret_cast<uint32_t*>(&h);
}

__device__ __forceinline__ float fast_sigmoid(float z) {
    float t = 0.5f * z;
    asm("tanh.approx.f32 %0, %0;" : "+f"(t));
    return fmaf(0.5f, t, 0.5f);
}

// ---------------------------------------------------------------------------
// One-time prep kernels (small)
// ---------------------------------------------------------------------------
__global__ void __launch_bounds__(256) cvt_x(const float* __restrict__ x)
{
    const size_t n = (size_t)N_NODES * XP;
    const size_t stride = (size_t)gridDim.x * blockDim.x;
    for (size_t i = (size_t)blockIdx.x * blockDim.x + threadIdx.x;
         i < n; i += stride) {
        size_t row = i >> 6;
        int c = (int)(i & 63);
        g_x32[i] = (c < NT) ? x[row * NT + c] : 0.0f;
    }
}

__global__ void __launch_bounds__(256) cvt_w(const float* __restrict__ W_hf,
                                             const float* __restrict__ W_if)
{
    const int n = HID * KW;
    for (int i = blockIdx.x * blockDim.x + threadIdx.x;
         i < n; i += gridDim.x * blockDim.x) {
        int row = i / KW, c = i % KW;
        float v = 0.0f;
        if (c < HID)            v = W_hf[row * HID + c];
        else if (c < HID + NT)  v = W_if[row * NT + (c - HID)];
        g_Wc[i] = __float2half_rn(v);
    }
}

// ---------------------------------------------------------------------------
// Fused GEMM + epilogue.
//   A: fp32 from h_all / g_x32, converted to fp16 in registers post-LDS.
//   B: fp16 g_Wc.  z = [h | x[seg]] @ Wc^T, K=320, BK=64, 2-stage cp.async.
//   A swizzle: 16B chunk q of row r at q^(r&1). B: q^((r&1)<<2).
//   Epilogue: 4 cols/thread (float4), tanh sigmoid, run-length segment-sum.
// grid = (2, 3125): N-half fastest -> A tile L2-reused across the pair.
// 256 threads = 8 warps, 4(m) x 2(n), warp tile 32x64. 2 CTAs/SM.
// ---------------------------------------------------------------------------
__global__ void __launch_bounds__(256, 2) fused_mma(
    const float* __restrict__ h_all, const float* __restrict__ c_all,
    const int*   __restrict__ seg,   const float* __restrict__ b_f,
    float* __restrict__ out)
{
    extern __shared__ float smf[];
    __shared__ int s_seg[BM];

    const int tid  = threadIdx.x;
    const int lane = tid & 31;
    const int warp = tid >> 5;
    const int wm = warp >> 1;          // 0..3
    const int wn = warp & 1;           // 0..1
    const int g  = lane >> 2, tg = lane & 3;
    const int n_off = blockIdx.x * BN;
    const size_t e0 = (size_t)blockIdx.y * BM;

    if (tid < BM) s_seg[tid] = seg[e0 + tid];
    __syncthreads();

    const uint32_t sbase = smem_u32(smf);

    // loader: A 128x64 fp32 (2048 16B chunks), B 128x64 fp16 (1024 chunks)
    auto load_chunk = [&](int kc, int stage) {
        const uint32_t ab = sbase + (uint32_t)stage * STG_BYTES;
        const uint32_t bb = ab + A_STG_B;
        #pragma unroll
        for (int t = 0; t < 8; ++t) {
            int idx = tid + 256 * t;
            int row = idx >> 4, q = idx & 15;
            uint32_t d = ab + (uint32_t)(row * 256 + ((q ^ (row & 1)) << 4));
            const float* src = (kc < 4)
                ? h_all + (e0 + row) * HID + kc * 64 + q * 4
                : g_x32 + (size_t)s_seg[row] * XP + q * 4;
            CP16(d, src);
        }
        #pragma unroll
        for (int t = 0; t < 4; ++t) {
            int idx = tid + 256 * t;
            int row = idx >> 3, q = idx & 7;
            uint32_t d = bb + (uint32_t)(row * 128 + ((q ^ ((row & 1) << 2)) << 4));
            CP16(d, g_Wc + (size_t)(n_off + row) * KW + kc * 64 + q * 8);
        }
    };

    load_chunk(0, 0); CP_COMMIT();
    load_chunk(1, 1); CP_COMMIT();

    float acc[2][8][4];
    #pragma unroll
    for (int i = 0; i < 2; ++i)
        #pragma unroll
        for (int j = 0; j < 8; ++j)
            #pragma unroll
            for (int q = 0; q < 4; ++q) acc[i][j][q] = 0.f;

    const int pr  = g & 1;             // A row parity for this thread
    const int psw = pr << 2;           // B chunk swizzle

    for (int kc = 0; kc < NCHUNK; ++kc) {
        CP_WAIT1();
        __syncthreads();

        const float*  Sa = smf + (kc & 1) * (STG_BYTES / 4);
        const __half* Sb = reinterpret_cast<const __half*>(Sa + BM * 64);

        #pragma unroll
        for (int wp = 0; wp < 2; ++wp) {
            const int p  = wp * 4 + tg;          // logical 8-half window
            const int cl = 2 * p + pr;           // phys chunk of logical 2p
            const int ch = 2 * p + 1 - pr;       // phys chunk of logical 2p+1
            const int pc = p ^ psw;              // B physical chunk

            // A fragments: load fp32, pack to fp16 pairs
            uint4 alo[2], ahi[2];
            #pragma unroll
            for (int i = 0; i < 2; ++i) {
                int r0 = wm * 32 + i * 16 + g;
                float4 La = *reinterpret_cast<const float4*>(Sa + r0 * 64 + cl * 4);
                float4 Lb = *reinterpret_cast<const float4*>(Sa + r0 * 64 + ch * 4);
                alo[i].x = packh2(La.x, La.y); alo[i].y = packh2(La.z, La.w);
                alo[i].z = packh2(Lb.x, Lb.y); alo[i].w = packh2(Lb.z, Lb.w);
                float4 Ha = *reinterpret_cast<const float4*>(Sa + (r0 + 8) * 64 + cl * 4);
                float4 Hb = *reinterpret_cast<const float4*>(Sa + (r0 + 8) * 64 + ch * 4);
                ahi[i].x = packh2(Ha.x, Ha.y); ahi[i].y = packh2(Ha.z, Ha.w);
                ahi[i].z = packh2(Hb.x, Hb.y); ahi[i].w = packh2(Hb.z, Hb.w);
            }
            uint4 bv[8];
            #pragma unroll
            for (int j = 0; j < 8; ++j) {
                int cn = wn * 64 + j * 8 + g;
                bv[j] = *reinterpret_cast<const uint4*>(
                    reinterpret_cast<const __half*>(Sb) + cn * 64 + pc * 8);
            }
            #pragma unroll
            for (int s = 0; s < 2; ++s) {
                #pragma unroll
                for (int i = 0; i < 2; ++i) {
                    uint32_t a0 = s ? alo[i].z : alo[i].x;
                    uint32_t a1 = s ? ahi[i].z : ahi[i].x;
                    uint32_t a2 = s ? alo[i].w : alo[i].y;
                    uint32_t a3 = s ? ahi[i].w : ahi[i].y;
                    #pragma unroll
                    for (int j = 0; j < 8; ++j) {
                        uint32_t b0 = s ? bv[j].z : bv[j].x;
                        uint32_t b1 = s ? bv[j].w : bv[j].y;
                        asm volatile(
                            "mma.sync.aligned.m16n8k16.row.col.f32.f16.f16.f32 "
                            "{%0,%1,%2,%3},{%4,%5,%6,%7},{%8,%9},{%0,%1,%2,%3};"
                            : "+f"(acc[i][j][0]), "+f"(acc[i][j][1]),
                              "+f"(acc[i][j][2]), "+f"(acc[i][j][3])
                            : "r"(a0), "r"(a1), "r"(a2), "r"(a3),
                              "r"(b0), "r"(b1));
                    }
                }
            }
        }

        __syncthreads();
        if (kc + 2 < NCHUNK) load_chunk(kc + 2, kc & 1);
        CP_COMMIT();
    }

    // ---- epilogue: stage z tile [128][132], then segmented reduce ----
    float* Sm = smf;
    #pragma unroll
    for (int i = 0; i < 2; ++i)
        #pragma unroll
        for (int j = 0; j < 8; ++j) {
            int row = wm * 32 + i * 16 + g;
            int col = wn * 64 + j * 8 + tg * 2;
            Sm[row * 132 + col]           = acc[i][j][0];
            Sm[row * 132 + col + 1]       = acc[i][j][1];
            Sm[(row + 8) * 132 + col]     = acc[i][j][2];
            Sm[(row + 8) * 132 + col + 1] = acc[i][j][3];
        }
    __syncthreads();

    // 4 cols per thread, 16 edges per thread
    const int cg    = tid & 31;
    const int col0l = cg * 4;
    const int col0  = n_off + col0l;
    const int ebase = (tid >> 5) * 16;
    const float4 bf = *reinterpret_cast<const float4*>(b_f + col0);

    float4 cv[8];
    #pragma unroll
    for (int u = 0; u < 8; ++u)
        cv[u] = *reinterpret_cast<const float4*>(
            c_all + (e0 + ebase + u) * HID + col0);

    int prev = -1;
    float a0 = 0.f, a1 = 0.f, a2 = 0.f, a3 = 0.f;
    #pragma unroll
    for (int half = 0; half < 2; ++half) {
        float4 nx[8];
        if (half == 0) {
            #pragma unroll
            for (int u = 0; u < 8; ++u)
                nx[u] = *reinterpret_cast<const float4*>(
                    c_all + (e0 + ebase + 8 + u) * HID + col0);
        }
        #pragma unroll
        for (int u = 0; u < 8; ++u) {
            int e = ebase + half * 8 + u;
            float4 zv = *reinterpret_cast<const float4*>(Sm + e * 132 + col0l);
            float f0 = cv[u].x * fast_sigmoid(zv.x + bf.x);
            float f1 = cv[u].y * fast_sigmoid(zv.y + bf.y);
            float f2 = cv[u].z * fast_sigmoid(zv.z + bf.z);
            float f3 = cv[u].w * fast_sigmoid(zv.w + bf.w);
            int node = s_seg[e];
            if (node != prev) {
                if (prev >= 0) {
                    float* o = out + (size_t)prev * HID + col0;
                    atomicAdd(o,     a0); atomicAdd(o + 1, a1);
                    atomicAdd(o + 2, a2); atomicAdd(o + 3, a3);
                }
                prev = node;
                a0 = a1 = a2 = a3 = 0.f;
            }
            a0 += f0; a1 += f1; a2 += f2; a3 += f3;
        }
        #pragma unroll
        for (int u = 0; u < 8; ++u) cv[u] = nx[u];
    }
    {
        float* o = out + (size_t)prev * HID + col0;
        atomicAdd(o,     a0); atomicAdd(o + 1, a1);
        atomicAdd(o + 2, a2); atomicAdd(o + 3, a3);
    }
}

// ---------------------------------------------------------------------------
extern "C" void kernel_launch(void* const* d_in, const int* in_sizes, int n_in,
                              void* d_out, int out_size)
{
    const float* x     = (const float*)d_in[0];
    const float* h_all = (const float*)d_in[1];
    const float* c_all = (const float*)d_in[2];
    const int*   seg   = (const int*)  d_in[3];
    const float* W_if  = (const float*)d_in[4];
    const float* W_hf  = (const float*)d_in[5];
    const float* b_f   = (const float*)d_in[6];
    float* out = (float*)d_out;

    cudaFuncSetAttribute(fused_mma,
        cudaFuncAttributeMaxDynamicSharedMemorySize, SMEM_DYN);

    cudaMemsetAsync(d_out, 0, (size_t)out_size * sizeof(float));
    cvt_x<<<4096, 256>>>(x);
    cvt_w<<<160, 256>>>(W_hf, W_if);
    dim3 grid(HID / BN, N_EDGES / BM);   // N-half fastest -> L2 A reuse
    fused_mma<<<grid, 256, SMEM_DYN>>>(h_all, c_all, seg, b_f, out);
}